// round 8
// baseline (speedup 1.0000x reference)
#include <cuda_runtime.h>

// B3-spline UWT (a trous), J=3. x:(16,1024,1024)f32 -> (16,4,1024,1024)f32.
// Per level: horizontal 5-tap via warp shuffles (1 aligned LDG.128/lane/row),
// h-rows staged in smem; vertical 5-tap as a sliding window over stride-DIL
// row chains (2 LDS/row); prev re-read from gmem (L1 hit). TY=64, 512 thr.

#define HH 1024
#define WW 1024
#define BB 16
#define HW (HH * WW)

__device__ float g_buf0[BB * HW];
__device__ float g_buf1[BB * HW];

__device__ __forceinline__ int refl(int i, int L) {
    if (i < 0) i = -i;
    if (i >= L) i = 2 * L - 2 - i;
    return i;
}

__device__ __forceinline__ float4 shfl_up4(float4 v, int d) {
    float4 r;
    r.x = __shfl_up_sync(0xFFFFFFFFu, v.x, d);
    r.y = __shfl_up_sync(0xFFFFFFFFu, v.y, d);
    r.z = __shfl_up_sync(0xFFFFFFFFu, v.z, d);
    r.w = __shfl_up_sync(0xFFFFFFFFu, v.w, d);
    return r;
}
__device__ __forceinline__ float4 shfl_dn4(float4 v, int d) {
    float4 r;
    r.x = __shfl_down_sync(0xFFFFFFFFu, v.x, d);
    r.y = __shfl_down_sync(0xFFFFFFFFu, v.y, d);
    r.z = __shfl_down_sync(0xFFFFFFFFu, v.z, d);
    r.w = __shfl_down_sync(0xFFFFFFFFu, v.w, d);
    return r;
}

__device__ __forceinline__ float4 ldrefl4(const float* row, int g0) {
    if (g0 >= 0 && g0 + 3 < WW) return *(const float4*)(row + g0);
    float4 v;
    v.x = row[refl(g0 + 0, WW)];
    v.y = row[refl(g0 + 1, WW)];
    v.z = row[refl(g0 + 2, WW)];
    v.w = row[refl(g0 + 3, WW)];
    return v;
}

template <int DIL>
__global__ __launch_bounds__(512, 3) void uwt_level(
    const float* __restrict__ in,     // (B,H,W) bstride HW
    float* __restrict__ detail,       // plane base, bstride 4*HW
    float* __restrict__ smooth,       // scratch (bstride HW) or c_J (4*HW)
    int sm_bs)
{
    constexpr int TX = 128, TY = 64;
    constexpr int SY  = TY + 4 * DIL;            // 68 / 72 / 80
    constexpr int NB  = (DIL == 4) ? 2 : 1;      // shuffle neighbors per side
    constexpr int CB  = 4 * NB;                  // center offset in window t[]
    constexpr int SMP = TX + 4;

    __shared__ float s_h[SY][SMP];

    const int b    = blockIdx.z;
    const int ty0  = blockIdx.y * TY;
    const int tx0  = blockIdx.x * TX;
    const int tid  = threadIdx.x;
    const int w    = tid >> 5;                   // 0..15
    const int lane = tid & 31;

    const float* base = in + b * HW;
    const int c0  = 4 * lane;
    const int gx0 = tx0 + c0;

    const float w0 = 0.0625f, w1 = 0.25f, w2 = 0.375f;

    // chain start for this warp (phase B rows rr = r0 + i*DIL, i=0..3)
    const int r0 = (w / DIL) * (4 * DIL) + (w % DIL);

    // ---- Phase A: horizontal conv of one image row -> s_h[r] --------------
    auto process_row = [&](int r, float4 v) {
        const int gy = refl(ty0 - 2 * DIL + r, HH);
        const float* row = base + gy * WW;

        float t[4 * (2 * NB + 1)];
        *(float4*)&t[CB] = v;
        #pragma unroll
        for (int d = 1; d <= NB; d++) {
            float4 a = shfl_up4(v, d);
            if (lane < d) a = ldrefl4(row, gx0 - 4 * d);
            *(float4*)&t[4 * (NB - d)] = a;
            float4 p = shfl_dn4(v, d);
            if (lane >= 32 - d) p = ldrefl4(row, gx0 + 4 * d);
            *(float4*)&t[4 * (NB + d)] = p;
        }

        float4 h;
        h.x = w0 * (t[CB + 0 - 2*DIL] + t[CB + 0 + 2*DIL])
            + w1 * (t[CB + 0 -   DIL] + t[CB + 0 +   DIL]) + w2 * t[CB + 0];
        h.y = w0 * (t[CB + 1 - 2*DIL] + t[CB + 1 + 2*DIL])
            + w1 * (t[CB + 1 -   DIL] + t[CB + 1 +   DIL]) + w2 * t[CB + 1];
        h.z = w0 * (t[CB + 2 - 2*DIL] + t[CB + 2 + 2*DIL])
            + w1 * (t[CB + 2 -   DIL] + t[CB + 2 +   DIL]) + w2 * t[CB + 2];
        h.w = w0 * (t[CB + 3 - 2*DIL] + t[CB + 3 + 2*DIL])
            + w1 * (t[CB + 3 -   DIL] + t[CB + 3 +   DIL]) + w2 * t[CB + 3];
        *(float4*)&s_h[r][c0] = h;
    };

    // Issue ALL of this warp's gmem loads first (4 chain rows + <=1 halo row),
    // then run the shuffle/FMA pipeline — maximizes MLP.
    {
        float4 v[4];
        #pragma unroll
        for (int i = 0; i < 4; i++) {
            const int gy = refl(ty0 + r0 + i * DIL, HH);   // = ty0-2D + (r0+2D+iD)
            v[i] = *(const float4*)(base + gy * WW + gx0);
        }

        // halo rows: s_h indices [0,2*DIL) and [2*DIL+TY, SY), one per warp
        float4 vh;
        int hr = -1;
        if (w < 4 * DIL) {
            hr = (w < 2 * DIL) ? w : w + TY;
            const int gyh = refl(ty0 - 2 * DIL + hr, HH);
            vh = *(const float4*)(base + gyh * WW + gx0);
        }

        #pragma unroll
        for (int i = 0; i < 4; i++)
            process_row(r0 + 2 * DIL + i * DIL, v[i]);
        if (hr >= 0)
            process_row(hr, vh);
    }
    __syncthreads();

    // ---- Phase B: vertical conv, sliding 5-row window over the chain ------
    float4 win[5];
    #pragma unroll
    for (int k = 0; k < 5; k++)
        win[k] = *(const float4*)&s_h[r0 + k * DIL][c0];

    #pragma unroll
    for (int i = 0; i < 4; i++) {
        const int rr  = r0 + i * DIL;
        const int off = (ty0 + rr) * WW + gx0;

        float4 prev = __ldg((const float4*)(base + off));   // L1 hit (phase A line)

        float4 sm;
        sm.x = w0 * (win[0].x + win[4].x) + w1 * (win[1].x + win[3].x) + w2 * win[2].x;
        sm.y = w0 * (win[0].y + win[4].y) + w1 * (win[1].y + win[3].y) + w2 * win[2].y;
        sm.z = w0 * (win[0].z + win[4].z) + w1 * (win[1].z + win[3].z) + w2 * win[2].z;
        sm.w = w0 * (win[0].w + win[4].w) + w1 * (win[1].w + win[3].w) + w2 * win[2].w;

        float4 dt = make_float4(prev.x - sm.x, prev.y - sm.y,
                                prev.z - sm.z, prev.w - sm.w);

        *(float4*)(detail + b * 4 * HW + off) = dt;
        *(float4*)(smooth + b * sm_bs  + off) = sm;

        if (i < 3) {
            win[0] = win[1]; win[1] = win[2]; win[2] = win[3]; win[3] = win[4];
            win[4] = *(const float4*)&s_h[r0 + (i + 5) * DIL][c0];
        }
    }
}

extern "C" void kernel_launch(void* const* d_in, const int* in_sizes, int n_in,
                              void* d_out, int out_size)
{
    (void)in_sizes; (void)n_in; (void)out_size;
    const float* x = (const float*)d_in[0];
    float* out = (float*)d_out;

    float *b0, *b1;
    cudaGetSymbolAddress((void**)&b0, g_buf0);
    cudaGetSymbolAddress((void**)&b1, g_buf1);

    dim3 grid(WW / 128, HH / 64, BB);
    dim3 block(512);

    uwt_level<1><<<grid, block>>>(x,  out + 0 * HW, b0, HW);
    uwt_level<2><<<grid, block>>>(b0, out + 1 * HW, b1, HW);
    uwt_level<4><<<grid, block>>>(b1, out + 2 * HW, out + 3 * HW, 4 * HW);
}

// round 9
// speedup vs baseline: 1.2107x; 1.2107x over previous
#include <cuda_runtime.h>

// B3-spline UWT (a trous), J=3. x:(16,1024,1024)f32 -> (16,4,1024,1024)f32.
// Per level, fully register-resident: vertical 5-tap conv first (per-lane,
// 8 streamed row loads per warp chain of 4 rows), then horizontal 5-tap via
// warp shuffles of the vertically-smoothed values. Edge lanes act as column
// halo (outputs from interior lanes only). No smem, no barriers.

#define HH 1024
#define WW 1024
#define BB 16
#define HW (HH * WW)

__device__ float g_buf0[BB * HW];
__device__ float g_buf1[BB * HW];

__device__ __forceinline__ int refl(int i, int L) {
    if (i < 0) i = -i;
    if (i >= L) i = 2 * L - 2 - i;
    return i;
}

__device__ __forceinline__ float4 shfl_up4(float4 v, int d) {
    float4 r;
    r.x = __shfl_up_sync(0xFFFFFFFFu, v.x, d);
    r.y = __shfl_up_sync(0xFFFFFFFFu, v.y, d);
    r.z = __shfl_up_sync(0xFFFFFFFFu, v.z, d);
    r.w = __shfl_up_sync(0xFFFFFFFFu, v.w, d);
    return r;
}
__device__ __forceinline__ float4 shfl_dn4(float4 v, int d) {
    float4 r;
    r.x = __shfl_down_sync(0xFFFFFFFFu, v.x, d);
    r.y = __shfl_down_sync(0xFFFFFFFFu, v.y, d);
    r.z = __shfl_down_sync(0xFFFFFFFFu, v.z, d);
    r.w = __shfl_down_sync(0xFFFFFFFFu, v.w, d);
    return r;
}

__device__ __forceinline__ float4 ldrefl4(const float* row, int g0) {
    if (g0 >= 0 && g0 + 3 < WW) return *(const float4*)(row + g0);
    float4 v;
    v.x = row[refl(g0 + 0, WW)];
    v.y = row[refl(g0 + 1, WW)];
    v.z = row[refl(g0 + 2, WW)];
    v.w = row[refl(g0 + 3, WW)];
    return v;
}

__device__ __forceinline__ float4 f4axpy(float4 a, float w, float4 v) {
    a.x += w * v.x; a.y += w * v.y; a.z += w * v.z; a.w += w * v.w;
    return a;
}

template <int DIL>
__global__ __launch_bounds__(256, 6) void uwt_level(
    const float* __restrict__ in,     // (B,H,W) bstride HW
    float* __restrict__ detail,       // plane base, bstride 4*HW
    float* __restrict__ smooth,       // scratch (bstride HW) or c_J (4*HW)
    int sm_bs)
{
    constexpr int TY = 32;
    constexpr int NB = (DIL == 4) ? 2 : 1;      // halo lanes per side
    constexpr int CB = 4 * NB;                  // center offset in window t[]

    const int b    = blockIdx.z;
    const int ty0  = blockIdx.y * TY;
    const int tid  = threadIdx.x;
    const int w    = tid >> 5;
    const int lane = tid & 31;

    constexpr int TXO = 4 * (32 - 2 * NB);      // 120 / 112 output cols per warp
    const int tx0 = blockIdx.x * TXO;
    const int gxv = tx0 + 4 * (lane - NB);      // this lane's load/output column

    const float* base = in + b * HW;
    const float w0 = 0.0625f, w1 = 0.25f, w2 = 0.375f;
    const float W5[5] = { w0, w1, w2, w1, w0 };

    // warp's chain rows: rr = r0 + i*DIL, i=0..3 (covers [0,TY) over 8 warps)
    const int r0 = (w / DIL) * (4 * DIL) + (w % DIL);

    // ---- vertical conv: stream 8 rows (r0 + (j-2)*DIL) into 4 accumulators
    float4 acc[4];
    #pragma unroll
    for (int i = 0; i < 4; i++) acc[i] = make_float4(0.f, 0.f, 0.f, 0.f);

    #pragma unroll
    for (int j = 0; j < 8; j++) {
        const int gy = refl(ty0 + r0 + (j - 2) * DIL, HH);
        float4 vj = ldrefl4(base + gy * WW, gxv);
        #pragma unroll
        for (int i = 0; i < 4; i++) {
            const int k = j - i;                // tap index for acc[i]
            if (k >= 0 && k <= 4) acc[i] = f4axpy(acc[i], W5[k], vj);
        }
    }

    // ---- horizontal conv via shuffles; interior lanes store outputs --------
    const bool doout = (lane >= NB) && (lane < 32 - NB) && (gxv < WW);

    #pragma unroll
    for (int i = 0; i < 4; i++) {
        float t[4 * (2 * NB + 1)];
        *(float4*)&t[CB] = acc[i];
        #pragma unroll
        for (int d = 1; d <= NB; d++) {
            *(float4*)&t[4 * (NB - d)] = shfl_up4(acc[i], d);
            *(float4*)&t[4 * (NB + d)] = shfl_dn4(acc[i], d);
        }

        if (doout) {
            float4 sm;
            sm.x = w0 * (t[CB + 0 - 2*DIL] + t[CB + 0 + 2*DIL])
                 + w1 * (t[CB + 0 -   DIL] + t[CB + 0 +   DIL]) + w2 * t[CB + 0];
            sm.y = w0 * (t[CB + 1 - 2*DIL] + t[CB + 1 + 2*DIL])
                 + w1 * (t[CB + 1 -   DIL] + t[CB + 1 +   DIL]) + w2 * t[CB + 1];
            sm.z = w0 * (t[CB + 2 - 2*DIL] + t[CB + 2 + 2*DIL])
                 + w1 * (t[CB + 2 -   DIL] + t[CB + 2 +   DIL]) + w2 * t[CB + 2];
            sm.w = w0 * (t[CB + 3 - 2*DIL] + t[CB + 3 + 2*DIL])
                 + w1 * (t[CB + 3 -   DIL] + t[CB + 3 +   DIL]) + w2 * t[CB + 3];

            const int off = (ty0 + r0 + i * DIL) * WW + gxv;
            float4 prev = *(const float4*)(base + off);    // L1 hit (just loaded)
            float4 dt = make_float4(prev.x - sm.x, prev.y - sm.y,
                                    prev.z - sm.z, prev.w - sm.w);

            *(float4*)(detail + b * 4 * HW + off) = dt;
            *(float4*)(smooth + b * sm_bs  + off) = sm;
        }
    }
}

extern "C" void kernel_launch(void* const* d_in, const int* in_sizes, int n_in,
                              void* d_out, int out_size)
{
    (void)in_sizes; (void)n_in; (void)out_size;
    const float* x = (const float*)d_in[0];
    float* out = (float*)d_out;

    float *b0, *b1;
    cudaGetSymbolAddress((void**)&b0, g_buf0);
    cudaGetSymbolAddress((void**)&b1, g_buf1);

    dim3 block(256);
    // TXO = 120 for DIL 1,2 -> 9 x-tiles; TXO = 112 for DIL 4 -> 10 x-tiles
    dim3 grid12((WW + 119) / 120, HH / 32, BB);
    dim3 grid4 ((WW + 111) / 112, HH / 32, BB);

    uwt_level<1><<<grid12, block>>>(x,  out + 0 * HW, b0, HW);
    uwt_level<2><<<grid12, block>>>(b0, out + 1 * HW, b1, HW);
    uwt_level<4><<<grid4,  block>>>(b1, out + 2 * HW, out + 3 * HW, 4 * HW);
}